// round 2
// baseline (speedup 1.0000x reference)
#include <cuda_runtime.h>
#include <cstdint>

// Resample2d: bilinear warp.
//   input1: (B=8, C=64, H=256, W=448) f32  image
//   input2: (B=8, 2,    H=256, W=448) f32  flow (dx = channel0, dy = channel1)
//   out:    (B=8, C=64, H=256, W=448) f32
//
// One thread per (b, y, x) pixel. Index math + weights computed once,
// reused across all 64 channels. Channel loop unrolled for MLP.

#define RS_B 8
#define RS_C 64
#define RS_H 256
#define RS_W 448
#define RS_HW (RS_H * RS_W)          // 114688
#define RS_PIX (RS_B * RS_HW)        // 917504

__global__ __launch_bounds__(256) void resample2d_kernel(
    const float* __restrict__ img,
    const float* __restrict__ flow,
    float* __restrict__ out)
{
    for (int pix = blockIdx.x * blockDim.x + threadIdx.x;
         pix < RS_PIX;
         pix += gridDim.x * blockDim.x)
    {
        int b = pix / RS_HW;
        int p = pix - b * RS_HW;
        int y = p / RS_W;
        int x = p - y * RS_W;

        // flow: dx at (b,0,y,x), dy at (b,1,y,x)
        const float* fl = flow + (size_t)b * 2 * RS_HW + p;
        float dx = __ldg(fl);
        float dy = __ldg(fl + RS_HW);

        float xf = (float)x + dx;
        float yf = (float)y + dy;
        float x0f = floorf(xf);
        float y0f = floorf(yf);
        float a  = xf - x0f;    // alpha
        float bt = yf - y0f;    // beta

        int x0 = min(max((int)x0f,     0), RS_W - 1);
        int x1 = min(max((int)x0f + 1, 0), RS_W - 1);
        int y0 = min(max((int)y0f,     0), RS_H - 1);
        int y1 = min(max((int)y0f + 1, 0), RS_H - 1);

        float w00 = (1.0f - a) * (1.0f - bt);
        float w10 = a          * (1.0f - bt);
        float w01 = (1.0f - a) * bt;
        float w11 = a          * bt;

        int i00 = y0 * RS_W + x0;
        int i10 = y0 * RS_W + x1;
        int i01 = y1 * RS_W + x0;
        int i11 = y1 * RS_W + x1;

        const float* pc = img + (size_t)b * RS_C * RS_HW;
        float*       o  = out + (size_t)b * RS_C * RS_HW + p;

        #pragma unroll 8
        for (int c = 0; c < RS_C; ++c) {
            float v = w00 * __ldg(pc + i00);
            v = fmaf(w10, __ldg(pc + i10), v);
            v = fmaf(w01, __ldg(pc + i01), v);
            v = fmaf(w11, __ldg(pc + i11), v);
            *o = v;
            pc += RS_HW;
            o  += RS_HW;
        }
    }
}

extern "C" void kernel_launch(void* const* d_in, const int* in_sizes, int n_in,
                              void* d_out, int out_size)
{
    const float* img  = (const float*)d_in[0];
    const float* flow = (const float*)d_in[1];
    float*       out  = (float*)d_out;

    const int threads = 256;
    const int blocks  = (RS_PIX + threads - 1) / threads;  // 3584
    resample2d_kernel<<<blocks, threads>>>(img, flow, out);
}

// round 3
// speedup vs baseline: 1.6713x; 1.6713x over previous
#include <cuda_runtime.h>
#include <cstdint>

// Resample2d bilinear warp, shared-memory staged gather version.
//   img:  (8, 64, 256, 448) f32
//   flow: (8, 2,  256, 448) f32  (dx = ch0, dy = ch1)
//   out:  (8, 64, 256, 448) f32
//
// Block = one batch x one 16-row output tile (full width). Per channel:
// stage rows [y_base-16, y_base+32] (49 rows) into smem via cp.async
// (double buffered), gather 4 taps per pixel from smem. Per-pixel index
// math is computed ONCE into registers and reused across all 64 channels.
// Rare pixels whose taps fall outside the staged window (|dy| > ~16,
// ~0.2%) take a global-memory fallback path.

#define RS_B 8
#define RS_C 64
#define RS_H 256
#define RS_W 448
#define RS_HW (RS_H * RS_W)            // 114688

#define ROWS_OUT 16
#define HALO_UP 16
#define HALO_DN 17
#define N_STAGE (ROWS_OUT + HALO_UP + HALO_DN)   // 49
#define STAGE_FLOATS (N_STAGE * RS_W)            // 21952
#define STAGE_VEC4 (STAGE_FLOATS / 4)            // 5488
#define NTHREADS 1024
#define PIX_PER_BLOCK (ROWS_OUT * RS_W)          // 7168
#define PIX_PER_THREAD (PIX_PER_BLOCK / NTHREADS) // 7
#define SMEM_BYTES (2 * STAGE_FLOATS * 4)        // 175616

__global__ void __launch_bounds__(NTHREADS, 1) resample2d_smem(
    const float* __restrict__ img,
    const float* __restrict__ flow,
    float* __restrict__ out)
{
    extern __shared__ float sbuf[];   // [2][STAGE_FLOATS]
    const int tid    = threadIdx.x;
    const int tile   = blockIdx.x & 15;   // 16 y-tiles
    const int b      = blockIdx.x >> 4;   // 8 batches
    const int y_base = tile * ROWS_OUT;
    const int y_lo   = y_base - HALO_UP;

    const float* gimg = img + (size_t)b * RS_C * RS_HW;
    float*       gout = out + (size_t)b * RS_C * RS_HW + (size_t)y_base * RS_W;

    uint32_t sbase = (uint32_t)__cvta_generic_to_shared(sbuf);

    // ---- issue staging for channel 0 immediately (overlaps precompute) ----
    {
        const float* plane = gimg;  // c = 0
        #pragma unroll
        for (int k = 0; k < 6; ++k) {
            int j = tid + k * NTHREADS;
            if (j < STAGE_VEC4) {
                int r  = j / (RS_W / 4);
                int cc = j % (RS_W / 4);
                int sy = min(max(y_lo + r, 0), RS_H - 1);
                const float* src = plane + sy * RS_W + cc * 4;
                asm volatile("cp.async.cg.shared.global [%0], [%1], 16;\n"
                             :: "r"(sbase + j * 16), "l"(src));
            }
        }
        asm volatile("cp.async.commit_group;\n");
    }

    // ---- precompute per-pixel params into registers (once for all 64 ch) ----
    uint4 prm[PIX_PER_THREAD];
    {
        const float* fl = flow + (size_t)b * 2 * RS_HW;
        #pragma unroll
        for (int k = 0; k < PIX_PER_THREAD; ++k) {
            int p = tid + k * NTHREADS;            // 0..7167
            int yl = p / RS_W;
            int x  = p - yl * RS_W;
            int y  = y_base + yl;
            int gi = y * RS_W + x;
            float dx = __ldg(fl + gi);
            float dy = __ldg(fl + RS_HW + gi);
            float xf  = (float)x + dx;
            float yf  = (float)y + dy;
            float x0f = floorf(xf);
            float y0f = floorf(yf);
            float a  = xf - x0f;
            float bt = yf - y0f;
            int x0 = min(max((int)x0f,     0), RS_W - 1);
            int x1 = min(max((int)x0f + 1, 0), RS_W - 1);
            int y0 = min(max((int)y0f,     0), RS_H - 1);
            int y1 = min(max((int)y0f + 1, 0), RS_H - 1);
            int s0 = y0 - y_lo;
            int s1 = y1 - y_lo;
            uint32_t lo, hi;
            if (s0 < 0 || s1 >= N_STAGE) {
                // fallback: pack global coords. bit31 = flag.
                lo = 0x80000000u | ((uint32_t)y0 << 9) | (uint32_t)x0;
                hi = ((uint32_t)y1 << 9) | (uint32_t)x1;
            } else {
                lo = (uint32_t)(s0 * RS_W + x0) | ((uint32_t)(s0 * RS_W + x1) << 16);
                hi = (uint32_t)(s1 * RS_W + x0) | ((uint32_t)(s1 * RS_W + x1) << 16);
            }
            prm[k] = make_uint4(__float_as_uint(a), __float_as_uint(bt), lo, hi);
        }
    }

    // ---- channel loop: double-buffered stage + compute ----
    for (int c = 0; c < RS_C; ++c) {
        if (c + 1 < RS_C) {
            const float* plane = gimg + (size_t)(c + 1) * RS_HW;
            uint32_t dst0 = sbase + ((c + 1) & 1) * (STAGE_FLOATS * 4);
            #pragma unroll
            for (int k = 0; k < 6; ++k) {
                int j = tid + k * NTHREADS;
                if (j < STAGE_VEC4) {
                    int r  = j / (RS_W / 4);
                    int cc = j % (RS_W / 4);
                    int sy = min(max(y_lo + r, 0), RS_H - 1);
                    const float* src = plane + sy * RS_W + cc * 4;
                    asm volatile("cp.async.cg.shared.global [%0], [%1], 16;\n"
                                 :: "r"(dst0 + j * 16), "l"(src));
                }
            }
            asm volatile("cp.async.commit_group;\n");
            asm volatile("cp.async.wait_group 1;\n");   // channel c staged
        } else {
            asm volatile("cp.async.wait_group 0;\n");
        }
        __syncthreads();   // staged data visible to all threads

        const float* sb    = sbuf + (c & 1) * STAGE_FLOATS;
        const float* plane = gimg + (size_t)c * RS_HW;   // fallback path
        float*       op    = gout + (size_t)c * RS_HW;

        #pragma unroll
        for (int k = 0; k < PIX_PER_THREAD; ++k) {
            int p = tid + k * NTHREADS;
            float a  = __uint_as_float(prm[k].x);
            float bt = __uint_as_float(prm[k].y);
            uint32_t lo = prm[k].z;
            uint32_t hi = prm[k].w;
            float v00, v10, v01, v11;
            if (!(lo & 0x80000000u)) {
                v00 = sb[lo & 0xFFFFu];
                v10 = sb[lo >> 16];
                v01 = sb[hi & 0xFFFFu];
                v11 = sb[hi >> 16];
            } else {
                int x0 = lo & 0x1FF;
                int y0 = (lo >> 9) & 0xFF;
                int x1 = hi & 0x1FF;
                int y1 = (hi >> 9) & 0xFF;
                v00 = __ldg(plane + y0 * RS_W + x0);
                v10 = __ldg(plane + y0 * RS_W + x1);
                v01 = __ldg(plane + y1 * RS_W + x0);
                v11 = __ldg(plane + y1 * RS_W + x1);
            }
            float om_a = 1.0f - a;
            float om_b = 1.0f - bt;
            float v = (om_a * om_b) * v00;
            v = fmaf(a * om_b, v10, v);
            v = fmaf(om_a * bt, v01, v);
            v = fmaf(a * bt,  v11, v);
            op[p] = v;
        }
        __syncthreads();   // protect buffer (c&1) before it is re-staged at c+2
    }
}

extern "C" void kernel_launch(void* const* d_in, const int* in_sizes, int n_in,
                              void* d_out, int out_size)
{
    const float* img  = (const float*)d_in[0];
    const float* flow = (const float*)d_in[1];
    float*       out  = (float*)d_out;

    cudaFuncSetAttribute(resample2d_smem,
                         cudaFuncAttributeMaxDynamicSharedMemorySize, SMEM_BYTES);

    // grid = 16 y-tiles * 8 batches = 128 blocks
    resample2d_smem<<<128, NTHREADS, SMEM_BYTES>>>(img, flow, out);
}